// round 2
// baseline (speedup 1.0000x reference)
#include <cuda_runtime.h>

typedef unsigned long long u64;

#define NB 2
#define NH 12
#define SQ 1024
#define DK 64
#define DM 768

// ---------------- scratch (static device globals; no allocation) ----------------
__device__ float g_q[NB*NH*SQ*DK];                 // [(b*12+h)*1024+s]*64+d, pre-scaled by 1/64
__device__ float g_k[NB*NH*SQ*DK];
__device__ float g_v[NB*NH*SQ*DK];
__device__ float g_scores[(size_t)NB*NH*SQ*SQ];    // [(b*12+h)*1024+q]*1024+k   (~100.7 MB)
__device__ float g_attn[NB*SQ*DM];                 // [b*1024+s]*768 + h*64+d

// ---------------- packed f32x2 helpers (sm_100+ PTX) ----------------
__device__ __forceinline__ u64 fpack(float x, float y){
    u64 r; asm("mov.b64 %0,{%1,%2};" : "=l"(r) : "f"(x), "f"(y)); return r;
}
__device__ __forceinline__ u64 ffma2(u64 a, u64 b, u64 c){
    u64 d; asm("fma.rn.f32x2 %0,%1,%2,%3;" : "=l"(d) : "l"(a), "l"(b), "l"(c)); return d;
}
__device__ __forceinline__ float2 funpack(u64 v){
    float x, y; asm("mov.b64 {%0,%1},%2;" : "=f"(x), "=f"(y) : "l"(v)); return make_float2(x, y);
}

// =====================================================================
// K1: QKV projections.  C[m,n] = scale * ( X[m,:] @ W[:,n] + bias[n] )
// BM=128, BN=64 (=one head), BK=16, 256 threads, 8x4 microtile.
// grid (16, 12, 3); z selects q/k/v.
// =====================================================================
__global__ __launch_bounds__(256) void k_proj(
    const float* __restrict__ Xq, const float* __restrict__ Xk, const float* __restrict__ Xv,
    const float* __restrict__ Wq, const float* __restrict__ Wk, const float* __restrict__ Wv,
    const float* __restrict__ bq, const float* __restrict__ bk, const float* __restrict__ bv)
{
    const int z = blockIdx.z;
    const float* X    = (z == 0) ? Xq : (z == 1) ? Xk : Xv;
    const float* W    = (z == 0) ? Wq : (z == 1) ? Wk : Wv;
    const float* bias = (z == 0) ? bq : (z == 1) ? bk : bv;
    float* out        = (z == 0) ? g_q : (z == 1) ? g_k : g_v;
    const float scale = (z == 0) ? (1.0f / 64.0f) : 1.0f;   // q: (d^-0.5)*(1/sqrt(d)) folded

    __shared__ __align__(16) float As[16][128];   // [k][m]
    __shared__ __align__(16) float Bs[16][64];    // [k][n]

    const int tid = threadIdx.x;
    const int tx = tid & 15, ty = tid >> 4;
    const int m0 = blockIdx.x * 128;
    const int h  = blockIdx.y;          // BN==64 == head width
    const int n0 = h * 64;

    u64 acc[8][2];
    #pragma unroll
    for (int i = 0; i < 8; i++) { acc[i][0] = 0ull; acc[i][1] = 0ull; }

    for (int k0 = 0; k0 < DM; k0 += 16) {
        #pragma unroll
        for (int it = 0; it < 2; it++) {
            int f = tid + it * 256;
            int m = f >> 2;
            int kk = (f & 3) * 4;
            float4 a4 = *(const float4*)(X + (size_t)(m0 + m) * DM + k0 + kk);
            As[kk + 0][m] = a4.x; As[kk + 1][m] = a4.y;
            As[kk + 2][m] = a4.z; As[kk + 3][m] = a4.w;
        }
        {
            int kk = tid >> 4;
            int nn = (tid & 15) * 4;
            *(float4*)&Bs[kk][nn] = *(const float4*)(W + (size_t)(k0 + kk) * DM + n0 + nn);
        }
        __syncthreads();
        #pragma unroll
        for (int k = 0; k < 16; k++) {
            float4 a0 = *(const float4*)&As[k][ty * 8];
            float4 a1 = *(const float4*)&As[k][ty * 8 + 4];
            ulonglong2 bu = *(const ulonglong2*)&Bs[k][tx * 4];
            float a[8] = {a0.x, a0.y, a0.z, a0.w, a1.x, a1.y, a1.z, a1.w};
            #pragma unroll
            for (int i = 0; i < 8; i++) {
                u64 ad = fpack(a[i], a[i]);
                acc[i][0] = ffma2(ad, bu.x, acc[i][0]);
                acc[i][1] = ffma2(ad, bu.y, acc[i][1]);
            }
        }
        __syncthreads();
    }

    float4 bb = *(const float4*)(bias + n0 + tx * 4);
    #pragma unroll
    for (int i = 0; i < 8; i++) {
        int m = m0 + ty * 8 + i;
        int b = m >> 10;
        int s = m & (SQ - 1);
        float2 p0 = funpack(acc[i][0]);
        float2 p1 = funpack(acc[i][1]);
        float4 o;
        o.x = (p0.x + bb.x) * scale;
        o.y = (p0.y + bb.y) * scale;
        o.z = (p1.x + bb.z) * scale;
        o.w = (p1.y + bb.w) * scale;
        *(float4*)(out + ((size_t)((b * NH + h) * SQ + s)) * DK + tx * 4) = o;
    }
}

// =====================================================================
// K2: scores = q @ k^T per (b,h).  M=N=1024, K=64.
// 128x128 tile, 8x8 microtile, whole K in smem (transposed, pad 132).
// grid (8, 8, 24). Dynamic smem 67584 B.
// =====================================================================
__global__ __launch_bounds__(256) void k_qk()
{
    extern __shared__ __align__(16) float sm[];
    float (*As)[132] = (float(*)[132])sm;             // [d][q]
    float (*Bs)[132] = (float(*)[132])(sm + 64 * 132);// [d][k]

    const int bh = blockIdx.z;
    const float* A  = g_q + (size_t)bh * SQ * DK;
    const float* Bm = g_k + (size_t)bh * SQ * DK;
    float* C = g_scores + (size_t)bh * SQ * SQ;

    const int m0 = blockIdx.x * 128;
    const int n0 = blockIdx.y * 128;
    const int tid = threadIdx.x;
    const int tx = tid & 15, ty = tid >> 4;

    #pragma unroll
    for (int it = 0; it < 8; it++) {
        int f = tid + it * 256;
        int m  = f >> 4;
        int d4 = (f & 15) * 4;
        float4 va = *(const float4*)(A  + (size_t)(m0 + m) * DK + d4);
        float4 vb = *(const float4*)(Bm + (size_t)(n0 + m) * DK + d4);
        As[d4 + 0][m] = va.x; As[d4 + 1][m] = va.y; As[d4 + 2][m] = va.z; As[d4 + 3][m] = va.w;
        Bs[d4 + 0][m] = vb.x; Bs[d4 + 1][m] = vb.y; Bs[d4 + 2][m] = vb.z; Bs[d4 + 3][m] = vb.w;
    }
    __syncthreads();

    u64 acc[8][4];
    #pragma unroll
    for (int i = 0; i < 8; i++)
        #pragma unroll
        for (int j = 0; j < 4; j++) acc[i][j] = 0ull;

    #pragma unroll 4
    for (int d = 0; d < 64; d++) {
        float4 a0 = *(const float4*)&As[d][ty * 8];
        float4 a1 = *(const float4*)&As[d][ty * 8 + 4];
        ulonglong2 b0 = *(const ulonglong2*)&Bs[d][tx * 8];
        ulonglong2 b1 = *(const ulonglong2*)&Bs[d][tx * 8 + 4];
        float a[8] = {a0.x, a0.y, a0.z, a0.w, a1.x, a1.y, a1.z, a1.w};
        #pragma unroll
        for (int i = 0; i < 8; i++) {
            u64 ad = fpack(a[i], a[i]);
            acc[i][0] = ffma2(ad, b0.x, acc[i][0]);
            acc[i][1] = ffma2(ad, b0.y, acc[i][1]);
            acc[i][2] = ffma2(ad, b1.x, acc[i][2]);
            acc[i][3] = ffma2(ad, b1.y, acc[i][3]);
        }
    }

    #pragma unroll
    for (int i = 0; i < 8; i++) {
        float2 p0 = funpack(acc[i][0]);
        float2 p1 = funpack(acc[i][1]);
        float2 p2 = funpack(acc[i][2]);
        float2 p3 = funpack(acc[i][3]);
        float4 o0 = make_float4(p0.x, p0.y, p1.x, p1.y);
        float4 o1 = make_float4(p2.x, p2.y, p3.x, p3.y);
        float* dst = C + (size_t)(m0 + ty * 8 + i) * SQ + n0 + tx * 8;
        *(float4*)(dst)     = o0;
        *(float4*)(dst + 4) = o1;
    }
}

// =====================================================================
// K3: scores[b,h,q,k] += q[b,h,q,:] . relation_k[b,q,k,:]
// CTA per (b,q). relK streamed in 128-row chunks via smem (pad 68).
// thread = (k_local, head-half of 6). grid (1024, 2).
// =====================================================================
__global__ __launch_bounds__(256) void k_qrel(const float* __restrict__ relk)
{
    __shared__ __align__(16) float rks[128][68];
    __shared__ __align__(16) float qs[NH * DK];

    const int b = blockIdx.y, q = blockIdx.x;
    const int tid = threadIdx.x;

    if (tid < 192) {
        int hh = tid >> 4;
        int d4 = (tid & 15) * 4;
        *(float4*)&qs[hh * DK + d4] =
            *(const float4*)(g_q + ((size_t)((b * NH + hh) * SQ + q)) * DK + d4);
    }

    const int klocal = tid & 127;
    const int hg = tid >> 7;                       // 0/1 -> heads [hg*6, hg*6+6)
    const float* relbase = relk + ((size_t)(b * SQ + q)) * SQ * DK;

    for (int kt = 0; kt < SQ; kt += 128) {
        __syncthreads();
        #pragma unroll
        for (int it = 0; it < 8; it++) {
            int f = tid + it * 256;
            int kk = f >> 4;
            int d4 = (f & 15) * 4;
            *(float4*)&rks[kk][d4] = *(const float4*)(relbase + (size_t)(kt + kk) * DK + d4);
        }
        __syncthreads();

        u64 acc2[6] = {0ull, 0ull, 0ull, 0ull, 0ull, 0ull};
        #pragma unroll
        for (int d4 = 0; d4 < 64; d4 += 4) {
            ulonglong2 r = *(const ulonglong2*)&rks[klocal][d4];
            #pragma unroll
            for (int j = 0; j < 6; j++) {
                ulonglong2 qv = *(const ulonglong2*)&qs[(hg * 6 + j) * DK + d4];
                acc2[j] = ffma2(qv.x, r.x, acc2[j]);
                acc2[j] = ffma2(qv.y, r.y, acc2[j]);
            }
        }
        #pragma unroll
        for (int j = 0; j < 6; j++) {
            int h = hg * 6 + j;
            float2 p = funpack(acc2[j]);
            float* dst = g_scores + ((size_t)((b * NH + h) * SQ + q)) * SQ + kt + klocal;
            *dst += p.x + p.y;
        }
    }
}

// =====================================================================
// K4: row softmax over last dim (1024). warp per row, 8 rows/CTA.
// grid (3072).
// =====================================================================
__global__ __launch_bounds__(256) void k_softmax()
{
    const int warp = threadIdx.x >> 5;
    const int lane = threadIdx.x & 31;
    const size_t row = (size_t)blockIdx.x * 8 + warp;
    float* p = g_scores + row * SQ;

    float4 v[8];
    float mx = -3.4e38f;
    #pragma unroll
    for (int j = 0; j < 8; j++) {
        v[j] = *(float4*)(p + lane * 4 + j * 128);
        mx = fmaxf(mx, fmaxf(fmaxf(v[j].x, v[j].y), fmaxf(v[j].z, v[j].w)));
    }
    #pragma unroll
    for (int o = 16; o > 0; o >>= 1) mx = fmaxf(mx, __shfl_xor_sync(0xffffffffu, mx, o));

    float s = 0.f;
    #pragma unroll
    for (int j = 0; j < 8; j++) {
        v[j].x = __expf(v[j].x - mx);
        v[j].y = __expf(v[j].y - mx);
        v[j].z = __expf(v[j].z - mx);
        v[j].w = __expf(v[j].w - mx);
        s += v[j].x + v[j].y + v[j].z + v[j].w;
    }
    #pragma unroll
    for (int o = 16; o > 0; o >>= 1) s += __shfl_xor_sync(0xffffffffu, s, o);
    const float inv = 1.0f / s;

    #pragma unroll
    for (int j = 0; j < 8; j++) {
        v[j].x *= inv; v[j].y *= inv; v[j].z *= inv; v[j].w *= inv;
        *(float4*)(p + lane * 4 + j * 128) = v[j];
    }
}

// =====================================================================
// K5: wv = probs @ v per (b,h).  M=1024, N=64, K=1024.
// BM=128, BN=64, BK=32, 8x4 microtile. grid (8, 24). Writes g_attn.
// =====================================================================
__global__ __launch_bounds__(256) void k_wv()
{
    __shared__ __align__(16) float As[32][132];   // [k][m]
    __shared__ __align__(16) float Bs[32][68];    // [k][d]

    const int bh = blockIdx.y;
    const int b = bh / NH, h = bh % NH;
    const float* A  = g_scores + (size_t)bh * SQ * SQ;
    const float* Bv = g_v + (size_t)bh * SQ * DK;

    const int m0 = blockIdx.x * 128;
    const int tid = threadIdx.x;
    const int tx = tid & 15, ty = tid >> 4;

    u64 acc[8][2];
    #pragma unroll
    for (int i = 0; i < 8; i++) { acc[i][0] = 0ull; acc[i][1] = 0ull; }

    for (int k0 = 0; k0 < SQ; k0 += 32) {
        #pragma unroll
        for (int it = 0; it < 4; it++) {
            int f = tid + it * 256;
            int m  = f >> 3;
            int k4 = (f & 7) * 4;
            float4 a4 = *(const float4*)(A + (size_t)(m0 + m) * SQ + k0 + k4);
            As[k4 + 0][m] = a4.x; As[k4 + 1][m] = a4.y;
            As[k4 + 2][m] = a4.z; As[k4 + 3][m] = a4.w;
        }
        #pragma unroll
        for (int it = 0; it < 2; it++) {
            int f = tid + it * 256;
            int kk = f >> 4;
            int d4 = (f & 15) * 4;
            *(float4*)&Bs[kk][d4] = *(const float4*)(Bv + (size_t)(k0 + kk) * DK + d4);
        }
        __syncthreads();
        #pragma unroll 8
        for (int k = 0; k < 32; k++) {
            float4 a0 = *(const float4*)&As[k][ty * 8];
            float4 a1 = *(const float4*)&As[k][ty * 8 + 4];
            ulonglong2 bu = *(const ulonglong2*)&Bs[k][tx * 4];
            float a[8] = {a0.x, a0.y, a0.z, a0.w, a1.x, a1.y, a1.z, a1.w};
            #pragma unroll
            for (int i = 0; i < 8; i++) {
                u64 ad = fpack(a[i], a[i]);
                acc[i][0] = ffma2(ad, bu.x, acc[i][0]);
                acc[i][1] = ffma2(ad, bu.y, acc[i][1]);
            }
        }
        __syncthreads();
    }

    #pragma unroll
    for (int i = 0; i < 8; i++) {
        int m = m0 + ty * 8 + i;
        float2 p0 = funpack(acc[i][0]);
        float2 p1 = funpack(acc[i][1]);
        float4 o = make_float4(p0.x, p0.y, p1.x, p1.y);
        *(float4*)(g_attn + (size_t)(b * SQ + m) * DM + h * DK + tx * 4) = o;
    }
}

// =====================================================================
// K6: g_attn[b,q,h*64+d] += sum_k probs[b,h,q,k] * relation_v[b,q,k,d]
// CTA per (b,q); relV streamed in 128-row chunks. thread = (d, 3 heads).
// grid (1024, 2).
// =====================================================================
__global__ __launch_bounds__(256) void k_wrel(const float* __restrict__ relv)
{
    __shared__ __align__(16) float rvs[128][68];
    __shared__ __align__(16) float ps[NH][128];

    const int b = blockIdx.y, q = blockIdx.x;
    const int tid = threadIdx.x;
    const int d  = tid & 63;
    const int hg = tid >> 6;                   // 0..3 -> heads {hg, hg+4, hg+8}
    const float* relbase = relv + ((size_t)(b * SQ + q)) * SQ * DK;

    u64 acc2[3] = {0ull, 0ull, 0ull};

    for (int kt = 0; kt < SQ; kt += 128) {
        __syncthreads();
        #pragma unroll
        for (int it = 0; it < 8; it++) {
            int f = tid + it * 256;
            int kk = f >> 4;
            int d4 = (f & 15) * 4;
            *(float4*)&rvs[kk][d4] = *(const float4*)(relbase + (size_t)(kt + kk) * DK + d4);
        }
        #pragma unroll
        for (int it = 0; it < 2; it++) {
            int f = tid + it * 256;
            if (f < 384) {
                int hh = f >> 5;
                int k4 = (f & 31) * 4;
                *(float4*)&ps[hh][k4] =
                    *(const float4*)(g_scores + ((size_t)((b * NH + hh) * SQ + q)) * SQ + kt + k4);
            }
        }
        __syncthreads();

        #pragma unroll 4
        for (int k4 = 0; k4 < 128; k4 += 4) {
            float rv0 = rvs[k4 + 0][d];
            float rv1 = rvs[k4 + 1][d];
            float rv2 = rvs[k4 + 2][d];
            float rv3 = rvs[k4 + 3][d];
            u64 rv01 = fpack(rv0, rv1);
            u64 rv23 = fpack(rv2, rv3);
            #pragma unroll
            for (int j = 0; j < 3; j++) {
                ulonglong2 pu = *(const ulonglong2*)&ps[hg + 4 * j][k4];
                acc2[j] = ffma2(pu.x, rv01, acc2[j]);
                acc2[j] = ffma2(pu.y, rv23, acc2[j]);
            }
        }
    }

    #pragma unroll
    for (int j = 0; j < 3; j++) {
        int h = hg + 4 * j;
        float2 p = funpack(acc2[j]);
        float* dst = g_attn + (size_t)(b * SQ + q) * DM + h * DK + d;
        *dst += p.x + p.y;
    }
}

// =====================================================================
// K7: output projection.  out = g_attn @ Wo + bo.  grid (16, 12).
// =====================================================================
__global__ __launch_bounds__(256) void k_out(
    const float* __restrict__ Wo, const float* __restrict__ bo, float* __restrict__ out)
{
    __shared__ __align__(16) float As[16][128];
    __shared__ __align__(16) float Bs[16][64];

    const int tid = threadIdx.x;
    const int tx = tid & 15, ty = tid >> 4;
    const int m0 = blockIdx.x * 128;
    const int n0 = blockIdx.y * 64;

    u64 acc[8][2];
    #pragma unroll
    for (int i = 0; i < 8; i++) { acc[i][0] = 0ull; acc[i][1] = 0ull; }

    for (int k0 = 0; k0 < DM; k0 += 16) {
        #pragma unroll
        for (int it = 0; it < 2; it++) {
            int f = tid + it * 256;
            int m = f >> 2;
            int kk = (f & 3) * 4;
            float4 a4 = *(const float4*)(g_attn + (size_t)(m0 + m) * DM + k0 + kk);
            As[kk + 0][m] = a4.x; As[kk + 1][m] = a4.y;
            As[kk + 2][m] = a4.z; As[kk + 3][m] = a4.w;
        }
        {
            int kk = tid >> 4;
            int nn = (tid & 15) * 4;
            *(float4*)&Bs[kk][nn] = *(const float4*)(Wo + (size_t)(k0 + kk) * DM + n0 + nn);
        }
        __syncthreads();
        #pragma unroll
        for (int k = 0; k < 16; k++) {
            float4 a0 = *(const float4*)&As[k][ty * 8];
            float4 a1 = *(const float4*)&As[k][ty * 8 + 4];
            ulonglong2 bu = *(const ulonglong2*)&Bs[k][tx * 4];
            float a[8] = {a0.x, a0.y, a0.z, a0.w, a1.x, a1.y, a1.z, a1.w};
            #pragma unroll
            for (int i = 0; i < 8; i++) {
                u64 ad = fpack(a[i], a[i]);
                acc[i][0] = ffma2(ad, bu.x, acc[i][0]);
                acc[i][1] = ffma2(ad, bu.y, acc[i][1]);
            }
        }
        __syncthreads();
    }

    float4 bb = *(const float4*)(bo + n0 + tx * 4);
    #pragma unroll
    for (int i = 0; i < 8; i++) {
        int m = m0 + ty * 8 + i;
        float2 p0 = funpack(acc[i][0]);
        float2 p1 = funpack(acc[i][1]);
        float4 o = make_float4(p0.x + bb.x, p0.y + bb.y, p1.x + bb.z, p1.y + bb.w);
        *(float4*)(out + (size_t)m * DM + n0 + tx * 4) = o;
    }
}

// =====================================================================
extern "C" void kernel_launch(void* const* d_in, const int* in_sizes, int n_in,
                              void* d_out, int out_size)
{
    // metadata order: queries, keys, values, relation_k, relation_v,
    //                 Wq, bq, Wk, bk, Wv, bv, Wo, bo
    const float* queries = (const float*)d_in[0];
    const float* keys    = (const float*)d_in[1];
    const float* values  = (const float*)d_in[2];
    const float* relk    = (const float*)d_in[3];
    const float* relv    = (const float*)d_in[4];
    const float* Wq = (const float*)d_in[5];
    const float* bq = (const float*)d_in[6];
    const float* Wk = (const float*)d_in[7];
    const float* bk = (const float*)d_in[8];
    const float* Wv = (const float*)d_in[9];
    const float* bv = (const float*)d_in[10];
    const float* Wo = (const float*)d_in[11];
    const float* bo = (const float*)d_in[12];
    float* out = (float*)d_out;

    // K1: projections
    k_proj<<<dim3(16, 12, 3), 256>>>(queries, keys, values, Wq, Wk, Wv, bq, bk, bv);

    // K2: qk^T
    static bool smem_set = false;
    if (!smem_set) {
        cudaFuncSetAttribute(k_qk, cudaFuncAttributeMaxDynamicSharedMemorySize,
                             2 * 64 * 132 * (int)sizeof(float));
        smem_set = true;
    }
    k_qk<<<dim3(8, 8, NB * NH), 256, 2 * 64 * 132 * sizeof(float)>>>();

    // K3: += q . relation_k
    k_qrel<<<dim3(SQ, NB), 256>>>(relk);

    // K4: softmax
    k_softmax<<<dim3(NB * NH * SQ / 8), 256>>>();

    // K5: probs @ v
    k_wv<<<dim3(8, NB * NH), 256>>>();

    // K6: += probs @ relation_v
    k_wrel<<<dim3(SQ, NB), 256>>>(relv);

    // K7: output projection
    k_out<<<dim3(16, 12), 256>>>(Wo, bo, out);
}